// round 2
// baseline (speedup 1.0000x reference)
#include <cuda_runtime.h>

#define INC   32
#define INN   50000
#define OUTC  32
#define OUTN  8192
#define MAXD  16
#define NB    8
#define NC    256   // N * INC

// 51.2 MB scratch for the transposed embedding table xT[i][n*32+c] = x[n][c][i]
__device__ float g_xT[(size_t)INN * NC];

// ---------------------------------------------------------------------------
// Kernel 1: tiled transpose x [256 rows x 50000 cols] -> g_xT [50000 x 256]
// ---------------------------------------------------------------------------
__global__ __launch_bounds__(256) void transpose_kernel(const float* __restrict__ x) {
    __shared__ float tile[32][33];
    const int i0 = blockIdx.x * 32;      // column tile (along INN)
    const int r0 = blockIdx.y * 32;      // row tile (along 256 = n*32+c)
    const int tx = threadIdx.x;
    const int ty = threadIdx.y;

    #pragma unroll
    for (int k = 0; k < 32; k += 8) {
        const int i = i0 + tx;
        const int r = r0 + ty + k;       // r < 256 always (gridDim.y = 8)
        tile[ty + k][tx] = (i < INN) ? x[(size_t)r * INN + i] : 0.0f;
    }
    __syncthreads();
    #pragma unroll
    for (int k = 0; k < 32; k += 8) {
        const int i = i0 + ty + k;
        if (i < INN)
            g_xT[(size_t)i * NC + (r0 + tx)] = tile[tx][ty + k];
    }
}

// ---------------------------------------------------------------------------
// Kernel 2: per block: 32 consecutive outputs o.
//   Phase A (pooling): thread tid owns (n,c)=(tid>>5, tid&31); for each o in
//     the tile, acc = sum_d mask[o,d] * xT[A[o,d]][tid]  (1 KB coalesced rows)
//   Phase B (GEMM+bias): thread tid owns (n,o)=(tid>>5, tid&31); computes all
//     32 outc so stores along o are 128B-coalesced.
// ---------------------------------------------------------------------------
__global__ __launch_bounds__(256) void pool_mm_kernel(
    const int*   __restrict__ A,
    const float* __restrict__ mask,
    const float* __restrict__ weight,
    const float* __restrict__ bias,
    float*       __restrict__ out)
{
    // pooled_s index: (n*32 + c)*33 + o  (pad 33 -> conflict-free both phases)
    __shared__ float pooled_s[NB * INC * 33];
    __shared__ float w_s[INC * OUTC];
    __shared__ int   a_s[32 * MAXD];
    __shared__ float m_s[32 * MAXD];

    const int tid    = threadIdx.x;
    const int o_base = blockIdx.x * 32;

    // Stage adjacency + mask for this o-tile (512 each) and weight (1024)
    #pragma unroll
    for (int k = 0; k < 2; ++k) {
        const int j = tid + k * 256;
        a_s[j] = A[o_base * MAXD + j];
        m_s[j] = mask[o_base * MAXD + j];
    }
    #pragma unroll
    for (int k = 0; k < 4; ++k)
        w_s[tid + k * 256] = weight[tid + k * 256];
    __syncthreads();

    // ---- Phase A: gather + masked mean-pool ----
    #pragma unroll 2
    for (int oo = 0; oo < 32; ++oo) {
        float acc = 0.0f;
        #pragma unroll
        for (int d = 0; d < MAXD; ++d) {
            const int   idx = a_s[oo * MAXD + d];     // broadcast
            const float m   = m_s[oo * MAXD + d];     // broadcast
            acc += m * g_xT[(size_t)idx * NC + tid];  // 1 KB coalesced row
        }
        pooled_s[tid * 33 + oo] = acc;                // bank = (tid+oo)%32, conflict-free
    }
    __syncthreads();

    // ---- Phase B: shared-weight matmul + bias, coalesced stores ----
    const int n = tid >> 5;
    const int o = tid & 31;
    #pragma unroll 4
    for (int outc = 0; outc < OUTC; ++outc) {
        float acc = bias[outc * OUTN + o_base + o];
        #pragma unroll
        for (int c = 0; c < INC; ++c)
            acc += pooled_s[(n * 32 + c) * 33 + o] * w_s[c * 32 + outc];
        out[(size_t)(n * OUTC + outc) * OUTN + o_base + o] = acc;
    }
}

// ---------------------------------------------------------------------------
// Launch
// ---------------------------------------------------------------------------
extern "C" void kernel_launch(void* const* d_in, const int* in_sizes, int n_in,
                              void* d_out, int out_size)
{
    const float* x      = (const float*)d_in[0];  // [8, 32, 50000] f32
    const int*   A      = (const int*)  d_in[1];  // [8192, 16] i32
    const float* mask   = (const float*)d_in[2];  // [8192, 16, 1] f32
    const float* weight = (const float*)d_in[3];  // [32, 32] f32
    const float* bias   = (const float*)d_in[4];  // [32, 8192] f32
    float*       out    = (float*)d_out;          // [8, 32, 8192] f32

    dim3 tb(32, 8);
    dim3 tg((INN + 31) / 32, NC / 32);
    transpose_kernel<<<tg, tb>>>(x);

    pool_mm_kernel<<<OUTN / 32, 256>>>(A, mask, weight, bias, out);
}

// round 3
// speedup vs baseline: 2.6267x; 2.6267x over previous
#include <cuda_runtime.h>

#define INC   32
#define INN   50000
#define OUTC  32
#define OUTN  8192
#define MAXD  16
#define NB    8
#define NC    256   // N * INC
#define TILE_O 16

// 51.2 MB scratch for the transposed embedding table xT[i][n*32+c] = x[n][c][i]
__device__ float g_xT[(size_t)INN * NC];

// ---------------------------------------------------------------------------
// Kernel 1: tiled transpose x [256 rows x 50000 cols] -> g_xT [50000 x 256]
// ---------------------------------------------------------------------------
__global__ __launch_bounds__(256) void transpose_kernel(const float* __restrict__ x) {
    __shared__ float tile[32][33];
    const int i0 = blockIdx.x * 32;      // column tile (along INN)
    const int r0 = blockIdx.y * 32;      // row tile (along 256 = n*32+c)
    const int tx = threadIdx.x;
    const int ty = threadIdx.y;

    #pragma unroll
    for (int k = 0; k < 32; k += 8) {
        const int i = i0 + tx;
        const int r = r0 + ty + k;       // r < 256 always (gridDim.y = 8)
        tile[ty + k][tx] = (i < INN) ? x[(size_t)r * INN + i] : 0.0f;
    }
    __syncthreads();
    #pragma unroll
    for (int k = 0; k < 32; k += 8) {
        const int i = i0 + ty + k;
        if (i < INN)
            g_xT[(size_t)i * NC + (r0 + tx)] = tile[tx][ty + k];
    }
}

// ---------------------------------------------------------------------------
// Kernel 2: per block: TILE_O=16 consecutive outputs o. Grid = 512.
//   Phase A: thread = (o_sub = tid>>6 in [0,4), col = tid&63 float4-column).
//     For each o-group, float4 acc over 16 neighbors: LDG.128 from 1KB rows.
//     pooled_s laid out [o][r] (stride 260) -> aligned float4 smem stores,
//     conflict-free (warp lanes write consecutive float4).
//   Phase B: thread = (half = tid>>7, n = (tid>>4)&7, o = tid&15); 16 outc
//     accumulators; w_s reads are warp-broadcast; stores coalesced along o.
// ---------------------------------------------------------------------------
__global__ __launch_bounds__(256, 4) void pool_mm_kernel(
    const int*   __restrict__ A,
    const float* __restrict__ mask,
    const float* __restrict__ weight,
    const float* __restrict__ bias,
    float*       __restrict__ out)
{
    __shared__ float pooled_s[TILE_O][260];   // [o][r], r = n*32+c; 260%4==0
    __shared__ float w_s[INC * OUTC];
    __shared__ int   a_s[TILE_O * MAXD];
    __shared__ float m_s[TILE_O * MAXD];

    const int tid    = threadIdx.x;
    const int o_base = blockIdx.x * TILE_O;

    // Stage adjacency + mask (256 each = blockDim) and weight (1024)
    a_s[tid] = A[o_base * MAXD + tid];
    m_s[tid] = mask[o_base * MAXD + tid];
    #pragma unroll
    for (int k = 0; k < 4; ++k)
        w_s[tid + k * 256] = weight[tid + k * 256];
    __syncthreads();

    // ---- Phase A: vectorized gather + masked mean-pool ----
    const float4* __restrict__ xT4 = (const float4*)g_xT;
    const int o_sub = tid >> 6;      // 0..3
    const int col   = tid & 63;      // float4 column (covers c-quad)

    #pragma unroll
    for (int g = 0; g < TILE_O / 4; ++g) {
        const int o = g * 4 + o_sub;
        float4 acc = make_float4(0.f, 0.f, 0.f, 0.f);
        #pragma unroll
        for (int d = 0; d < MAXD; ++d) {
            const int   idx = a_s[o * MAXD + d];   // warp-broadcast
            const float m   = m_s[o * MAXD + d];   // warp-broadcast
            const float4 v  = xT4[(size_t)idx * (NC / 4) + col];  // LDG.128
            acc.x += m * v.x; acc.y += m * v.y;
            acc.z += m * v.z; acc.w += m * v.w;
        }
        *(float4*)&pooled_s[o][col * 4] = acc;     // aligned, conflict-free
    }
    __syncthreads();

    // ---- Phase B: shared-weight matmul + bias ----
    const int o    = tid & (TILE_O - 1);   // 0..15
    const int n    = (tid >> 4) & 7;       // 0..7
    const int half = tid >> 7;             // 0..1 -> owns 16 outc

    float acc[16];
    #pragma unroll
    for (int k = 0; k < 16; ++k)
        acc[k] = bias[(half * 16 + k) * OUTN + o_base + o];

    #pragma unroll
    for (int c = 0; c < INC; ++c) {
        const float p = pooled_s[o][n * 32 + c];
        #pragma unroll
        for (int k = 0; k < 16; ++k)
            acc[k] += p * w_s[c * 32 + half * 16 + k];  // broadcast
    }

    #pragma unroll
    for (int k = 0; k < 16; ++k)
        out[(size_t)(n * OUTC + half * 16 + k) * OUTN + o_base + o] = acc[k];
}

// ---------------------------------------------------------------------------
// Launch
// ---------------------------------------------------------------------------
extern "C" void kernel_launch(void* const* d_in, const int* in_sizes, int n_in,
                              void* d_out, int out_size)
{
    const float* x      = (const float*)d_in[0];  // [8, 32, 50000] f32
    const int*   A      = (const int*)  d_in[1];  // [8192, 16] i32
    const float* mask   = (const float*)d_in[2];  // [8192, 16, 1] f32
    const float* weight = (const float*)d_in[3];  // [32, 32] f32
    const float* bias   = (const float*)d_in[4];  // [32, 8192] f32
    float*       out    = (float*)d_out;          // [8, 32, 8192] f32

    dim3 tb(32, 8);
    dim3 tg((INN + 31) / 32, NC / 32);
    transpose_kernel<<<tg, tb>>>(x);

    pool_mm_kernel<<<OUTN / TILE_O, 256>>>(A, mask, weight, bias, out);
}